// round 13
// baseline (speedup 1.0000x reference)
#include <cuda_runtime.h>
#include <cuda_bf16.h>
#include <cstdint>

// ---------------- problem constants ----------------
#define BATCH   4
#define LSEQ    2048
#define CIN     128
#define DMODEL  256
#define DIP     1824
#define DINNER  768
#define NHEADS  256
#define NSTATE  16
#define CONVD   800
#define MROWS   (BATCH*LSEQ)
#define QCHUNK  32
#define NCHK    (LSEQ/QCHUNK)    // 64 chunks

typedef unsigned long long ull;
typedef __nv_bfloat16 bf16;

// ---------------- scratch ----------------
__device__ bf16  g_xth[MROWS*CIN];
__device__ bf16  g_xtl[MROWS*CIN];
__device__ bf16  g_pwh[DMODEL*512];
__device__ bf16  g_pwl[DMODEL*512];
__device__ bf16  g_uh [MROWS*DMODEL];
__device__ bf16  g_ul [MROWS*DMODEL];
__device__ bf16  g_wih[DIP*DMODEL];
__device__ bf16  g_wil[DIP*DMODEL];
__device__ bf16  g_owh[DMODEL*DINNER];
__device__ bf16  g_owl[DMODEL*DINNER];
__device__ bf16  g_ynh[MROWS*DINNER];
__device__ bf16  g_ynl[MROWS*DINNER];
__device__ float g_zx [MROWS*DIP];
__device__ float g_xs [MROWS*DINNER];
__device__ float g_Bm [MROWS*NSTATE];
__device__ float g_Cm [MROWS*NSTATE];
__device__ float g_dt [MROWS*NHEADS];
__device__ float g_dA [MROWS*NHEADS];
__device__ float g_LS [BATCH*NCHK*NHEADS*48];
__device__ float g_Dc [BATCH*NCHK*NHEADS];
__device__ float g_h0 [BATCH*NCHK*NHEADS*48];
__device__ float g_yr [MROWS*DINNER];

// ---------------- f32x2 helpers ----------------
__device__ __forceinline__ ull pack2(float lo, float hi) {
    ull r; asm("mov.b64 %0, {%1,%2};" : "=l"(r) : "f"(lo), "f"(hi)); return r;
}
__device__ __forceinline__ void unpack2(ull v, float& lo, float& hi) {
    asm("mov.b64 {%0,%1}, %2;" : "=f"(lo), "=f"(hi) : "l"(v));
}
__device__ __forceinline__ ull fma2(ull a, ull b, ull c) {
    ull r; asm("fma.rn.f32x2 %0, %1, %2, %3;" : "=l"(r) : "l"(a), "l"(b), "l"(c)); return r;
}
__device__ __forceinline__ ull mul2(ull a, ull b) {
    ull r; asm("mul.rn.f32x2 %0, %1, %2;" : "=l"(r) : "l"(a), "l"(b)); return r;
}

// ---------------- mma / cp.async helpers ----------------
__device__ __forceinline__ uint32_t s2u(const void* p) {
    uint32_t a;
    asm("{ .reg .u64 t; cvta.to.shared.u64 t, %1; cvt.u32.u64 %0, t; }" : "=r"(a) : "l"(p));
    return a;
}
__device__ __forceinline__ uint32_t bfpack(float lo, float hi) {
    uint32_t r; asm("cvt.rn.bf16x2.f32 %0, %1, %2;" : "=r"(r) : "f"(hi), "f"(lo)); return r;
}
__device__ __forceinline__ void ldsm_x4(uint32_t* r, uint32_t addr) {
    asm volatile("ldmatrix.sync.aligned.m8n8.x4.shared.b16 {%0,%1,%2,%3}, [%4];"
        : "=r"(r[0]), "=r"(r[1]), "=r"(r[2]), "=r"(r[3]) : "r"(addr));
}
__device__ __forceinline__ void ldsm_x2(uint32_t* r, uint32_t addr) {
    asm volatile("ldmatrix.sync.aligned.m8n8.x2.shared.b16 {%0,%1}, [%2];"
        : "=r"(r[0]), "=r"(r[1]) : "r"(addr));
}
__device__ __forceinline__ void mma_bf16(float* c, const uint32_t* a, const uint32_t* b) {
    asm volatile("mma.sync.aligned.m16n8k16.row.col.f32.bf16.bf16.f32 "
        "{%0,%1,%2,%3}, {%4,%5,%6,%7}, {%8,%9}, {%0,%1,%2,%3};"
        : "+f"(c[0]), "+f"(c[1]), "+f"(c[2]), "+f"(c[3])
        : "r"(a[0]), "r"(a[1]), "r"(a[2]), "r"(a[3]), "r"(b[0]), "r"(b[1]));
}
__device__ __forceinline__ void cpa16(uint32_t dst, const void* src, int sz) {
    asm volatile("cp.async.cg.shared.global [%0], [%1], 16, %2;"
        :: "r"(dst), "l"(src), "r"(sz) : "memory");
}
#define CP_COMMIT() asm volatile("cp.async.commit_group;" ::: "memory")
#define CP_WAIT0()  asm volatile("cp.async.wait_group 0;" ::: "memory")
#define CP_WAIT1()  asm volatile("cp.async.wait_group 1;" ::: "memory")

__device__ __forceinline__ void split_store(bf16* ph, bf16* pl, int idx, float v) {
    bf16 h = __float2bfloat16(v);
    ph[idx] = h;
    pl[idx] = __float2bfloat16(v - __bfloat162float(h));
}

// ---------------- pipelined bf16 GEMM ----------------
// C[m,n] = sum_k (Ahi+Alo)[m,k]*(Bhi+Blo)[n,k] (3-product split)
// 8 warps (2x4), warp tile 64x32, K-chunk 32.
// STAGES=2: frozen R4 config, 80KB smem (2 CTA/SM for big grids).
// STAGES=3: 122KB smem ring, 2-iteration load slack — for grid<=148 launches
//           (occupancy is 1 CTA/SM regardless, extra smem free).
// MODE 0: C[m*Ndim+n] fp32
// MODE 1: C[(n>>11)*524288 + m*2048 + (n&2047)] fp32
// MODE 2: Ch/Cl[m*Ndim+n] bf16 hi/lo
// CONV 1: A = virtual im2col of (MROWS,128): col -> tap=co>>7, ch=co&127, row m+tap-1.
#define SROW   80
#define STILE  (128*SROW)      // 10240
#define SBUF   (4*STILE)       // 40960 per stage
template<int MODE, int CONV, int STAGES>
__global__ void __launch_bounds__(256) k_gemm_mma(
        const bf16* __restrict__ Ahi, const bf16* __restrict__ Alo,
        const bf16* __restrict__ Bhi, const bf16* __restrict__ Blo,
        float* __restrict__ C, bf16* __restrict__ Ch, bf16* __restrict__ Cl,
        int Ndim, int Kdim) {
    extern __shared__ __align__(16) unsigned char smem[];
    uint32_t sb = s2u(smem);
    int tid = threadIdx.x, lane = tid & 31, wid = tid >> 5;
    int bm = blockIdx.y * 128, bn = blockIdx.x * 128;
    int wm = wid & 1, wn = wid >> 1;

    float acc[4][4][4];
    #pragma unroll
    for (int i = 0; i < 4; i++)
        #pragma unroll
        for (int j = 0; j < 4; j++)
            #pragma unroll
            for (int q = 0; q < 4; q++) acc[i][j][q] = 0.f;

    int crow = tid >> 2, cseg = tid & 3;
    uint32_t dst0 = (uint32_t)crow * SROW + (uint32_t)cseg * 16;
    const bf16* asrc[2] = { Ahi, Alo };
    const bf16* bsrc[2] = { Bhi, Blo };
    int bok0 = (bn + crow)      < Ndim;
    int bok1 = (bn + crow + 64) < Ndim;
    int brow0 = bok0 ? bn + crow      : 0;
    int brow1 = bok1 ? bn + crow + 64 : 0;

    int nch = Kdim >> 5;

    auto load_stage = [&](int kc, int buf) {
        int k0 = kc << 5;
        uint32_t base = sb + (uint32_t)buf * SBUF + dst0;
        if (CONV) {
            int co  = k0 + cseg * 8;
            int tap = co >> 7, ch = co & 127;
            int m0a = bm + crow, m1a = bm + crow + 64;
            int ls0 = (m0a & (LSEQ - 1)) + tap - 1;
            int ls1 = (m1a & (LSEQ - 1)) + tap - 1;
            int ok0 = (ls0 >= 0 && ls0 < LSEQ) ? 16 : 0;
            int ok1 = (ls1 >= 0 && ls1 < LSEQ) ? 16 : 0;
            size_t off0 = (size_t)(m0a + tap - 1) * CIN + ch;
            size_t off1 = (size_t)(m1a + tap - 1) * CIN + ch;
            #pragma unroll
            for (int t = 0; t < 2; t++) {
                cpa16(base + t * STILE,             asrc[t] + off0, ok0);
                cpa16(base + t * STILE + 64 * SROW, asrc[t] + off1, ok1);
                const bf16* sb0 = bsrc[t] + (size_t)brow0 * Kdim + k0 + cseg * 8;
                const bf16* sb1 = bsrc[t] + (size_t)brow1 * Kdim + k0 + cseg * 8;
                cpa16(base + (2 + t) * STILE,             sb0, bok0 ? 16 : 0);
                cpa16(base + (2 + t) * STILE + 64 * SROW, sb1, bok1 ? 16 : 0);
            }
        } else {
            size_t co = (size_t)k0 + cseg * 8;
            #pragma unroll
            for (int t = 0; t < 2; t++) {
                const bf16* sa0 = asrc[t] + (size_t)(bm + crow)      * Kdim + co;
                const bf16* sa1 = asrc[t] + (size_t)(bm + crow + 64) * Kdim + co;
                cpa16(base + t * STILE,             sa0, 16);
                cpa16(base + t * STILE + 64 * SROW, sa1, 16);
                const bf16* sb0 = bsrc[t] + (size_t)brow0 * Kdim + co;
                const bf16* sb1 = bsrc[t] + (size_t)brow1 * Kdim + co;
                cpa16(base + (2 + t) * STILE,             sb0, bok0 ? 16 : 0);
                cpa16(base + (2 + t) * STILE + 64 * SROW, sb1, bok1 ? 16 : 0);
            }
        }
    };

    uint32_t ra_off = (uint32_t)(wm * 64 + (lane & 15)) * SROW + ((lane >> 4) * 8) * 2;
    uint32_t rb_off = 2 * STILE + (uint32_t)(wn * 32 + (lane & 7)) * SROW + (((lane >> 3) & 1) * 8) * 2;

    auto mma_chunk = [&](uint32_t stg) {
        #pragma unroll
        for (int kk = 0; kk < 2; kk++) {
            uint32_t ah[4][4], al[4][4], bh[4][2], bl[4][2];
            #pragma unroll
            for (int i = 0; i < 4; i++) {
                uint32_t ra = stg + ra_off + (uint32_t)(i * 16) * SROW + kk * 32;
                ldsm_x4(ah[i], ra);
                ldsm_x4(al[i], ra + STILE);
            }
            #pragma unroll
            for (int j = 0; j < 4; j++) {
                uint32_t rb = stg + rb_off + (uint32_t)(j * 8) * SROW + kk * 32;
                ldsm_x2(bh[j], rb);
                ldsm_x2(bl[j], rb + STILE);
            }
            #pragma unroll
            for (int i = 0; i < 4; i++)
                #pragma unroll
                for (int j = 0; j < 4; j++) {
                    mma_bf16(acc[i][j], ah[i], bh[j]);
                    mma_bf16(acc[i][j], ah[i], bl[j]);
                    mma_bf16(acc[i][j], al[i], bh[j]);
                }
        }
    };

    if (STAGES == 2) {
        // frozen R4 loop
        load_stage(0, 0);
        CP_COMMIT();
        for (int kc = 0; kc < nch; kc++) {
            if (kc + 1 < nch) {
                load_stage(kc + 1, (kc + 1) & 1);
                CP_COMMIT();
                CP_WAIT1();
            } else {
                CP_WAIT0();
            }
            __syncthreads();
            mma_chunk(sb + (uint32_t)(kc & 1) * SBUF);
            __syncthreads();
        }
    } else {
        // 3-stage ring, one barrier per iteration
        load_stage(0, 0); CP_COMMIT();
        load_stage(1, 1); CP_COMMIT();
        int buf = 0, nbuf = 2;
        for (int kc = 0; kc < nch; kc++) {
            if (kc + 1 < nch) { CP_WAIT1(); } else { CP_WAIT0(); }
            __syncthreads();   // data for chunk kc visible; prior MMAs (kc-1) done -> nbuf reusable
            if (kc + 2 < nch) {
                load_stage(kc + 2, nbuf);
                CP_COMMIT();
            }
            mma_chunk(sb + (uint32_t)buf * SBUF);
            buf  = (buf  == 2) ? 0 : buf  + 1;
            nbuf = (nbuf == 2) ? 0 : nbuf + 1;
        }
    }

    int r0 = lane >> 2, c0l = (lane & 3) * 2;
    #pragma unroll
    for (int i = 0; i < 4; i++) {
        int m = bm + wm * 64 + i * 16 + r0;
        #pragma unroll
        for (int j = 0; j < 4; j++) {
            int n = bn + wn * 32 + j * 8 + c0l;
            if (MODE == 0) {
                if (n + 2 <= Ndim) {
                    *reinterpret_cast<float2*>(C + (size_t)m * Ndim + n) =
                        make_float2(acc[i][j][0], acc[i][j][1]);
                    *reinterpret_cast<float2*>(C + (size_t)(m + 8) * Ndim + n) =
                        make_float2(acc[i][j][2], acc[i][j][3]);
                }
            } else if (MODE == 1) {
                size_t idx = (size_t)(n >> 11) * (256 * 2048) + (size_t)m * 2048 + (n & 2047);
                *reinterpret_cast<float2*>(C + idx) = make_float2(acc[i][j][0], acc[i][j][1]);
                *reinterpret_cast<float2*>(C + idx + 8 * 2048) = make_float2(acc[i][j][2], acc[i][j][3]);
            } else {
                #pragma unroll
                for (int h = 0; h < 2; h++) {
                    float v0 = acc[i][j][h * 2], v1 = acc[i][j][h * 2 + 1];
                    uint32_t hp = bfpack(v0, v1);
                    __nv_bfloat162 hb = *reinterpret_cast<__nv_bfloat162*>(&hp);
                    uint32_t lp = bfpack(v0 - __bfloat162float(hb.x), v1 - __bfloat162float(hb.y));
                    size_t idx = (size_t)(m + h * 8) * Ndim + n;
                    *reinterpret_cast<uint32_t*>(Ch + idx) = hp;
                    *reinterpret_cast<uint32_t*>(Cl + idx) = lp;
                }
            }
        }
    }
}

// ---------------- transpose x (b,c,l) -> (b*l, c) bf16 hi/lo ----------------
__global__ void k_txp(const float* __restrict__ x) {
    __shared__ uint32_t t[32][33];
    int b = blockIdx.z;
    int l0 = blockIdx.x * 32, c0 = blockIdx.y * 32;
    int tx = threadIdx.x, ty = threadIdx.y;   // 32 x 8
    #pragma unroll
    for (int j = 0; j < 32; j += 8) {
        float v = x[(size_t)(b * CIN + c0 + ty + j) * LSEQ + l0 + tx];
        bf16 h = __float2bfloat16(v);
        bf16 l = __float2bfloat16(v - __bfloat162float(h));
        t[ty + j][tx] = (uint32_t)__bfloat16_as_ushort(h)
                      | ((uint32_t)__bfloat16_as_ushort(l) << 16);
    }
    __syncthreads();
    unsigned short* xth = reinterpret_cast<unsigned short*>(g_xth);
    unsigned short* xtl = reinterpret_cast<unsigned short*>(g_xtl);
    #pragma unroll
    for (int j = 0; j < 32; j += 8) {
        int ly = ty + j;
        uint32_t p = t[tx][ly];
        size_t idx = (size_t)(b * LSEQ + l0 + ly) * CIN + c0 + tx;
        xth[idx] = (unsigned short)(p & 0xffffu);
        xtl[idx] = (unsigned short)(p >> 16);
    }
}

__global__ void k_pwpack(const float* __restrict__ pw) {
    int tid = blockIdx.x * blockDim.x + threadIdx.x;
    int d = tid >> 9, r = tid & 511;
    int k = r >> 7, c = r & 127;
    split_store(g_pwh, g_pwl, tid, pw[(d * CIN + c) * 4 + k]);
}

// merged weight conversion (in_proj + out_proj)
__global__ void k_wcvt2(const float* __restrict__ w1, const float* __restrict__ w2) {
    int tid = blockIdx.x * blockDim.x + threadIdx.x;
    if (tid < DIP * DMODEL) {
        split_store(g_wih, g_wil, tid, w1[tid]);
    } else {
        int t2 = tid - DIP * DMODEL;
        if (t2 < DMODEL * DINNER) split_store(g_owh, g_owl, t2, w2[t2]);
    }
}

// ---------------- depthwise conv + silu + split + dt/dA (8 rows/block) ----------------
#define CTR 8
__global__ void __launch_bounds__(256) k_conv(const float* __restrict__ cw,
                                              const float* __restrict__ cb,
                                              const float* __restrict__ dt_bias,
                                              const float* __restrict__ A_log) {
    __shared__ float s[(CTR + 3) * CONVD];
    int m0 = blockIdx.x * CTR;
    int l0 = m0 & (LSEQ - 1);
    int tid = threadIdx.x;
    for (int i = tid; i < (CTR + 3) * CONVD; i += 256) {
        int r = i / CONVD, c = i - r * CONVD;
        float v = 0.f;
        if (l0 - 3 + r >= 0)
            v = g_zx[(size_t)(m0 - 3 + r) * DIP + DINNER + c];
        s[i] = v;
    }
    {
        int hh = tid;
        float db = dt_bias[hh];
        float An = -expf(A_log[hh]);
        #pragma unroll
        for (int rr = 0; rr < CTR; rr++) {
            int m = m0 + rr;
            float v = g_zx[(size_t)m * DIP + 1568 + hh] + db;
            float sp = (v > 20.f) ? v : log1pf(expf(v));
            g_dt[m * NHEADS + hh] = sp;
            g_dA[m * NHEADS + hh] = expf(sp * An);
        }
    }
    __syncthreads();
    for (int c = tid; c < CONVD; c += 256) {
        float4 w4 = *reinterpret_cast<const float4*>(cw + c * 4);
        float cbv = cb[c];
        #pragma unroll
        for (int rr = 0; rr < CTR; rr++) {
            float a = cbv + s[rr * CONVD + c] * w4.x + s[(rr + 1) * CONVD + c] * w4.y
                          + s[(rr + 2) * CONVD + c] * w4.z + s[(rr + 3) * CONVD + c] * w4.w;
            float act = a / (1.f + expf(-a));
            int m = m0 + rr;
            if (c < DINNER)    g_xs[(size_t)m * DINNER + c] = act;
            else if (c < 784)  g_Bm[m * NSTATE + c - DINNER] = act;
            else               g_Cm[m * NSTATE + c - 784] = act;
        }
    }
}

// ---------------- per-chunk local scan (QCHUNK=32, 256 blocks) ----------------
__global__ void __launch_bounds__(256) k_scan_local() {
    __shared__ float Bsh[QCHUNK * NSTATE];
    int blk = blockIdx.x;
    int hh = threadIdx.x;
    int m0 = (blk / NCHK) * LSEQ + (blk % NCHK) * QCHUNK;
    for (int i = hh; i < QCHUNK * NSTATE; i += 256) Bsh[i] = g_Bm[(size_t)m0 * NSTATE + i];
    __syncthreads();

    ull st[3][8];
    #pragma unroll
    for (int p = 0; p < 3; p++)
        #pragma unroll
        for (int q = 0; q < 8; q++) st[p][q] = 0ull;
    float dc = 1.f;

    #pragma unroll 2
    for (int s = 0; s < QCHUNK; s++) {
        size_t m = (size_t)m0 + s;
        float a  = g_dA[m * NHEADS + hh];
        float dv = g_dt[m * NHEADS + hh];
        float x0 = g_xs[m * DINNER + hh*3 + 0];
        float x1 = g_xs[m * DINNER + hh*3 + 1];
        float x2 = g_xs[m * DINNER + hh*3 + 2];
        ull a2 = pack2(a, a);
        float w0 = dv * x0, w1 = dv * x1, w2 = dv * x2;
        ull v0 = pack2(w0, w0), v1 = pack2(w1, w1), v2 = pack2(w2, w2);
        dc *= a;
        const float2* Bp = reinterpret_cast<const float2*>(Bsh + s * NSTATE);
        #pragma unroll
        for (int q = 0; q < 8; q++) {
            float2 bf = Bp[q];
            ull b2 = pack2(bf.x, bf.y);
            st[0][q] = fma2(a2, st[0][q], mul2(v0, b2));
            st[1][q] = fma2(a2, st[1][q], mul2(v1, b2));
            st[2][q] = fma2(a2, st[2][q], mul2(v2, b2));
        }
    }
    ull* outp = reinterpret_cast<ull*>(g_LS) + ((size_t)blk * NHEADS + hh) * 24;
    #pragma unroll
    for (int p = 0; p < 3; p++)
        #pragma unroll
        for (int q = 0; q < 8; q++) outp[p * 8 + q] = st[p][q];
    g_Dc[blk * NHEADS + hh] = dc;
}

// ---------------- cross-chunk scan ----------------
__global__ void k_cross() {
    int tid = blockIdx.x * blockDim.x + threadIdx.x;   // 24576
    int q  = tid % 24;
    int bh = tid / 24;
    int b  = bh >> 8, hh = bh & 255;
    ull cur = 0ull;
    const ull* LSp = reinterpret_cast<const ull*>(g_LS);
    ull* H0p = reinterpret_cast<ull*>(g_h0);
    for (int c = 0; c < NCHK; c++) {
        size_t off = ((size_t)(b * NCHK + c) * NHEADS + hh) * 24 + q;
        H0p[off] = cur;
        float dc = g_Dc[(b * NCHK + c) * NHEADS + hh];
        cur = fma2(pack2(dc, dc), cur, LSp[off]);
    }
}

// ---------------- per-chunk scan with init state, emit y ----------------
__global__ void __launch_bounds__(256) k_scan_out(const float* __restrict__ Dsk) {
    __shared__ float Bsh[QCHUNK * NSTATE];
    __shared__ float Csh[QCHUNK * NSTATE];
    int blk = blockIdx.x;
    int hh = threadIdx.x;
    int m0 = (blk / NCHK) * LSEQ + (blk % NCHK) * QCHUNK;
    for (int i = hh; i < QCHUNK * NSTATE; i += 256) {
        Bsh[i] = g_Bm[(size_t)m0 * NSTATE + i];
        Csh[i] = g_Cm[(size_t)m0 * NSTATE + i];
    }
    __syncthreads();

    ull st[3][8];
    const ull* hp = reinterpret_cast<const ull*>(g_h0) + ((size_t)blk * NHEADS + hh) * 24;
    #pragma unroll
    for (int p = 0; p < 3; p++)
        #pragma unroll
        for (int q = 0; q < 8; q++) st[p][q] = hp[p * 8 + q];
    float ds = Dsk[hh];

    #pragma unroll 2
    for (int s = 0; s < QCHUNK; s++) {
        size_t m = (size_t)m0 + s;
        float a  = g_dA[m * NHEADS + hh];
        float dv = g_dt[m * NHEADS + hh];
        float x0 = g_xs[m * DINNER + hh*3 + 0];
        float x1 = g_xs[m * DINNER + hh*3 + 1];
        float x2 = g_xs[m * DINNER + hh*3 + 2];
        ull a2 = pack2(a, a);
        float w0 = dv * x0, w1 = dv * x1, w2 = dv * x2;
        ull v0 = pack2(w0, w0), v1 = pack2(w1, w1), v2 = pack2(w2, w2);
        const float2* Bp = reinterpret_cast<const float2*>(Bsh + s * NSTATE);
        const float2* Cp = reinterpret_cast<const float2*>(Csh + s * NSTATE);
        ull y0 = 0ull, y1 = 0ull, y2 = 0ull;
        #pragma unroll
        for (int q = 0; q < 8; q++) {
            float2 bf = Bp[q];
            float2 cf = Cp[q];
            ull b2 = pack2(bf.x, bf.y);
            ull c2 = pack2(cf.x, cf.y);
            st[0][q] = fma2(a2, st[0][q], mul2(v0, b2));
            st[1][q] = fma2(a2, st[1][q], mul2(v1, b2));
            st[2][q] = fma2(a2, st[2][q], mul2(v2, b2));
            y0 = fma2(st[0][q], c2, y0);
            y1 = fma2(st[1][q], c2, y1);
            y2 = fma2(st[2][q], c2, y2);
        }
        float lo, hi;
        float* yo = g_yr + m * DINNER + hh * 3;
        unpack2(y0, lo, hi); yo[0] = lo + hi + ds * x0;
        unpack2(y1, lo, hi); yo[1] = lo + hi + ds * x1;
        unpack2(y2, lo, hi); yo[2] = lo + hi + ds * x2;
    }
}

// ---------------- gate with silu(z) + RMSNorm -> bf16 hi/lo ----------------
__global__ void k_norm(const float* __restrict__ nw) {
    int m = blockIdx.x;
    int tid = threadIdx.x;
    float vals[3];
    float ss = 0.f;
    #pragma unroll
    for (int j = 0; j < 3; j++) {
        int c = tid + j * 256;
        float z = g_zx[(size_t)m * DIP + c];
        float y = g_yr[(size_t)m * DINNER + c] * (z / (1.f + expf(-z)));
        vals[j] = y;
        ss += y * y;
    }
    #pragma unroll
    for (int o = 16; o > 0; o >>= 1) ss += __shfl_xor_sync(0xffffffffu, ss, o);
    __shared__ float red[8];
    if ((tid & 31) == 0) red[tid >> 5] = ss;
    __syncthreads();
    float tot = 0.f;
    #pragma unroll
    for (int w = 0; w < 8; w++) tot += red[w];
    float r = rsqrtf(tot * (1.f / 768.f) + 1e-5f);
    #pragma unroll
    for (int j = 0; j < 3; j++) {
        int c = tid + j * 256;
        split_store(g_ynh, g_ynl, m * DINNER + c, vals[j] * r * nw[c]);
    }
}

// ---------------- launch ----------------
extern "C" void kernel_launch(void* const* d_in, const int* in_sizes, int n_in,
                              void* d_out, int out_size) {
    const float* x        = (const float*)d_in[0];
    const float* proj_w   = (const float*)d_in[1];
    const float* in_proj  = (const float*)d_in[2];
    const float* conv_w   = (const float*)d_in[3];
    const float* conv_b   = (const float*)d_in[4];
    const float* dt_bias  = (const float*)d_in[5];
    const float* A_log    = (const float*)d_in[6];
    const float* D_skip   = (const float*)d_in[7];
    const float* norm_w   = (const float*)d_in[8];
    const float* out_proj = (const float*)d_in[9];
    float* out = (float*)d_out;

    bf16 *xth, *xtl, *pwh, *pwl, *uh, *ul, *wih, *wil, *owh, *owl, *ynh, *ynl;
    float *zx;
    cudaGetSymbolAddress((void**)&xth, g_xth); cudaGetSymbolAddress((void**)&xtl, g_xtl);
    cudaGetSymbolAddress((void**)&pwh, g_pwh); cudaGetSymbolAddress((void**)&pwl, g_pwl);
    cudaGetSymbolAddress((void**)&uh,  g_uh);  cudaGetSymbolAddress((void**)&ul,  g_ul);
    cudaGetSymbolAddress((void**)&wih, g_wih); cudaGetSymbolAddress((void**)&wil, g_wil);
    cudaGetSymbolAddress((void**)&owh, g_owh); cudaGetSymbolAddress((void**)&owl, g_owl);
    cudaGetSymbolAddress((void**)&ynh, g_ynh); cudaGetSymbolAddress((void**)&ynl, g_ynl);
    cudaGetSymbolAddress((void**)&zx,  g_zx);

    const int SM2 = 2 * SBUF;   // 81920
    const int SM3 = 3 * SBUF;   // 122880
    static int inited = 0;
    if (!inited) {
        cudaFuncSetAttribute((const void*)k_gemm_mma<0,0,2>, cudaFuncAttributeMaxDynamicSharedMemorySize, SM2);
        cudaFuncSetAttribute((const void*)k_gemm_mma<1,0,3>, cudaFuncAttributeMaxDynamicSharedMemorySize, SM3);
        cudaFuncSetAttribute((const void*)k_gemm_mma<2,1,3>, cudaFuncAttributeMaxDynamicSharedMemorySize, SM3);
        inited = 1;
    }

    k_txp<<<dim3(LSEQ/32, CIN/32, BATCH), dim3(32, 8)>>>(x);
    k_pwpack<<<(DMODEL*512)/256, 256>>>(proj_w);
    k_wcvt2<<<(DIP*DMODEL + DMODEL*DINNER + 255)/256, 256>>>(in_proj, out_proj);

    // conv-proj (virtual im2col, 3-stage): u = conv(x) @ pw^T (M=8192, N=256, K=512)
    k_gemm_mma<2,1,3><<<dim3(2, 64), 256, SM3>>>(xth, xtl, pwh, pwl, nullptr, uh, ul, DMODEL, 512);
    // in_proj (frozen 2-stage, 2 CTA/SM): zx = u @ w^T (M=8192, N=1824, K=256)
    k_gemm_mma<0,0,2><<<dim3(15, 64), 256, SM2>>>(uh, ul, wih, wil, zx, nullptr, nullptr, DIP, DMODEL);

    k_conv<<<MROWS/CTR, 256>>>(conv_w, conv_b, dt_bias, A_log);

    k_scan_local<<<BATCH*NCHK, NHEADS>>>();
    k_cross<<<96, 256>>>();
    k_scan_out<<<BATCH*NCHK, NHEADS>>>(D_skip);

    k_norm<<<MROWS, 256>>>(norm_w);

    // out_proj (3-stage): outT = ow @ yn^T (M=256, N=8192, K=768), transposed store
    k_gemm_mma<1,0,3><<<dim3(64, 2), 256, SM3>>>(owh, owl, ynh, ynl, out, nullptr, nullptr, MROWS, DINNER);
}

// round 15
// speedup vs baseline: 1.0024x; 1.0024x over previous
#include <cuda_runtime.h>
#include <cuda_bf16.h>
#include <cstdint>

// ---------------- problem constants ----------------
#define BATCH   4
#define LSEQ    2048
#define CIN     128
#define DMODEL  256
#define DIP     1824
#define DINNER  768
#define NHEADS  256
#define NSTATE  16
#define CONVD   800
#define MROWS   (BATCH*LSEQ)
#define QCHUNK  32
#define NCHK    (LSEQ/QCHUNK)    // 64 chunks

typedef unsigned long long ull;
typedef __nv_bfloat16 bf16;

// ---------------- scratch ----------------
__device__ bf16  g_xth[MROWS*CIN];
__device__ bf16  g_xtl[MROWS*CIN];
__device__ bf16  g_pwh[DMODEL*512];
__device__ bf16  g_pwl[DMODEL*512];
__device__ bf16  g_uh [MROWS*DMODEL];
__device__ bf16  g_ul [MROWS*DMODEL];
__device__ bf16  g_wih[DIP*DMODEL];
__device__ bf16  g_wil[DIP*DMODEL];
__device__ bf16  g_owh[DMODEL*DINNER];
__device__ bf16  g_owl[DMODEL*DINNER];
__device__ bf16  g_ynh[MROWS*DINNER];
__device__ bf16  g_ynl[MROWS*DINNER];
__device__ float g_zx [MROWS*DIP];
__device__ float g_xs [MROWS*DINNER];
__device__ float g_Bm [MROWS*NSTATE];
__device__ float g_Cm [MROWS*NSTATE];
__device__ float g_dt [MROWS*NHEADS];
__device__ float g_dA [MROWS*NHEADS];
__device__ float g_LS [BATCH*NCHK*NHEADS*48];
__device__ float g_Dc [BATCH*NCHK*NHEADS];
__device__ float g_h0 [BATCH*NCHK*NHEADS*48];
__device__ float g_yr [MROWS*DINNER];

// ---------------- f32x2 helpers ----------------
__device__ __forceinline__ ull pack2(float lo, float hi) {
    ull r; asm("mov.b64 %0, {%1,%2};" : "=l"(r) : "f"(lo), "f"(hi)); return r;
}
__device__ __forceinline__ void unpack2(ull v, float& lo, float& hi) {
    asm("mov.b64 {%0,%1}, %2;" : "=f"(lo), "=f"(hi) : "l"(v));
}
__device__ __forceinline__ ull fma2(ull a, ull b, ull c) {
    ull r; asm("fma.rn.f32x2 %0, %1, %2, %3;" : "=l"(r) : "l"(a), "l"(b), "l"(c)); return r;
}
__device__ __forceinline__ ull mul2(ull a, ull b) {
    ull r; asm("mul.rn.f32x2 %0, %1, %2;" : "=l"(r) : "l"(a), "l"(b)); return r;
}

// ---------------- mma / cp.async helpers ----------------
__device__ __forceinline__ uint32_t s2u(const void* p) {
    uint32_t a;
    asm("{ .reg .u64 t; cvta.to.shared.u64 t, %1; cvt.u32.u64 %0, t; }" : "=r"(a) : "l"(p));
    return a;
}
__device__ __forceinline__ uint32_t bfpack(float lo, float hi) {
    uint32_t r; asm("cvt.rn.bf16x2.f32 %0, %1, %2;" : "=r"(r) : "f"(hi), "f"(lo)); return r;
}
__device__ __forceinline__ void ldsm_x4(uint32_t* r, uint32_t addr) {
    asm volatile("ldmatrix.sync.aligned.m8n8.x4.shared.b16 {%0,%1,%2,%3}, [%4];"
        : "=r"(r[0]), "=r"(r[1]), "=r"(r[2]), "=r"(r[3]) : "r"(addr));
}
__device__ __forceinline__ void ldsm_x2(uint32_t* r, uint32_t addr) {
    asm volatile("ldmatrix.sync.aligned.m8n8.x2.shared.b16 {%0,%1}, [%2];"
        : "=r"(r[0]), "=r"(r[1]) : "r"(addr));
}
__device__ __forceinline__ void mma_bf16(float* c, const uint32_t* a, const uint32_t* b) {
    asm volatile("mma.sync.aligned.m16n8k16.row.col.f32.bf16.bf16.f32 "
        "{%0,%1,%2,%3}, {%4,%5,%6,%7}, {%8,%9}, {%0,%1,%2,%3};"
        : "+f"(c[0]), "+f"(c[1]), "+f"(c[2]), "+f"(c[3])
        : "r"(a[0]), "r"(a[1]), "r"(a[2]), "r"(a[3]), "r"(b[0]), "r"(b[1]));
}
__device__ __forceinline__ void cpa16(uint32_t dst, const void* src, int sz) {
    asm volatile("cp.async.cg.shared.global [%0], [%1], 16, %2;"
        :: "r"(dst), "l"(src), "r"(sz) : "memory");
}
#define CP_COMMIT() asm volatile("cp.async.commit_group;" ::: "memory")
#define CP_WAIT0()  asm volatile("cp.async.wait_group 0;" ::: "memory")
#define CP_WAIT1()  asm volatile("cp.async.wait_group 1;" ::: "memory")

__device__ __forceinline__ void split_store(bf16* ph, bf16* pl, int idx, float v) {
    bf16 h = __float2bfloat16(v);
    ph[idx] = h;
    pl[idx] = __float2bfloat16(v - __bfloat162float(h));
}

#define SROW   80
#define STILE  (128*SROW)      // 10240
#define SBUF   (4*STILE)       // 40960 per stage

// ---------------- 256-thread pipelined bf16 GEMM (FROZEN R4: 2-stage, 2 CTA/SM) ----------
// MODE 0: C[m*Ndim+n] fp32
template<int MODE>
__global__ void __launch_bounds__(256) k_gemm_mma(
        const bf16* __restrict__ Ahi, const bf16* __restrict__ Alo,
        const bf16* __restrict__ Bhi, const bf16* __restrict__ Blo,
        float* __restrict__ C, bf16* __restrict__ Ch, bf16* __restrict__ Cl,
        int Ndim, int Kdim) {
    extern __shared__ __align__(16) unsigned char smem[];
    uint32_t sb = s2u(smem);
    int tid = threadIdx.x, lane = tid & 31, wid = tid >> 5;
    int bm = blockIdx.y * 128, bn = blockIdx.x * 128;
    int wm = wid & 1, wn = wid >> 1;

    float acc[4][4][4];
    #pragma unroll
    for (int i = 0; i < 4; i++)
        #pragma unroll
        for (int j = 0; j < 4; j++)
            #pragma unroll
            for (int q = 0; q < 4; q++) acc[i][j][q] = 0.f;

    int crow = tid >> 2, cseg = tid & 3;
    uint32_t dst0 = (uint32_t)crow * SROW + (uint32_t)cseg * 16;
    const bf16* asrc[2] = { Ahi, Alo };
    const bf16* bsrc[2] = { Bhi, Blo };
    int bok0 = (bn + crow)      < Ndim;
    int bok1 = (bn + crow + 64) < Ndim;
    int brow0 = bok0 ? bn + crow      : 0;
    int brow1 = bok1 ? bn + crow + 64 : 0;

    int nch = Kdim >> 5;

    auto load_stage = [&](int kc, int buf) {
        int k0 = kc << 5;
        uint32_t base = sb + (uint32_t)buf * SBUF + dst0;
        size_t co = (size_t)k0 + cseg * 8;
        #pragma unroll
        for (int t = 0; t < 2; t++) {
            const bf16* sa0 = asrc[t] + (size_t)(bm + crow)      * Kdim + co;
            const bf16* sa1 = asrc[t] + (size_t)(bm + crow + 64) * Kdim + co;
            cpa16(base + t * STILE,             sa0, 16);
            cpa16(base + t * STILE + 64 * SROW, sa1, 16);
            const bf16* sb0 = bsrc[t] + (size_t)brow0 * Kdim + co;
            const bf16* sb1 = bsrc[t] + (size_t)brow1 * Kdim + co;
            cpa16(base + (2 + t) * STILE,             sb0, bok0 ? 16 : 0);
            cpa16(base + (2 + t) * STILE + 64 * SROW, sb1, bok1 ? 16 : 0);
        }
    };

    load_stage(0, 0);
    CP_COMMIT();

    uint32_t ra_off = (uint32_t)(wm * 64 + (lane & 15)) * SROW + ((lane >> 4) * 8) * 2;
    uint32_t rb_off = 2 * STILE + (uint32_t)(wn * 32 + (lane & 7)) * SROW + (((lane >> 3) & 1) * 8) * 2;

    for (int kc = 0; kc < nch; kc++) {
        if (kc + 1 < nch) {
            load_stage(kc + 1, (kc + 1) & 1);
            CP_COMMIT();
            CP_WAIT1();
        } else {
            CP_WAIT0();
        }
        __syncthreads();
        uint32_t stg = sb + (uint32_t)(kc & 1) * SBUF;
        #pragma unroll
        for (int kk = 0; kk < 2; kk++) {
            uint32_t ah[4][4], al[4][4], bh[4][2], bl[4][2];
            #pragma unroll
            for (int i = 0; i < 4; i++) {
                uint32_t ra = stg + ra_off + (uint32_t)(i * 16) * SROW + kk * 32;
                ldsm_x4(ah[i], ra);
                ldsm_x4(al[i], ra + STILE);
            }
            #pragma unroll
            for (int j = 0; j < 4; j++) {
                uint32_t rb = stg + rb_off + (uint32_t)(j * 8) * SROW + kk * 32;
                ldsm_x2(bh[j], rb);
                ldsm_x2(bl[j], rb + STILE);
            }
            #pragma unroll
            for (int i = 0; i < 4; i++)
                #pragma unroll
                for (int j = 0; j < 4; j++) {
                    mma_bf16(acc[i][j], ah[i], bh[j]);
                    mma_bf16(acc[i][j], ah[i], bl[j]);
                    mma_bf16(acc[i][j], al[i], bh[j]);
                }
        }
        __syncthreads();
    }

    int r0 = lane >> 2, c0l = (lane & 3) * 2;
    #pragma unroll
    for (int i = 0; i < 4; i++) {
        int m = bm + wm * 64 + i * 16 + r0;
        #pragma unroll
        for (int j = 0; j < 4; j++) {
            int n = bn + wn * 32 + j * 8 + c0l;
            if (n + 2 <= Ndim) {
                *reinterpret_cast<float2*>(C + (size_t)m * Ndim + n) =
                    make_float2(acc[i][j][0], acc[i][j][1]);
                *reinterpret_cast<float2*>(C + (size_t)(m + 8) * Ndim + n) =
                    make_float2(acc[i][j][2], acc[i][j][3]);
            }
        }
    }
}

// ---------------- 16-warp (512-thread) GEMM for grid<=148 launches ----------------
// Same 128x128 tile, SROW-80 layout, 3-stage ring, identical math order.
// 4x4 warp grid, 32x32 warp tile -> 4 warps/SMSP of issue parallelism at 1 CTA/SM.
// MODE 1: C[(n>>11)*524288 + m*2048 + (n&2047)] fp32  (transposed out)
// MODE 2: Ch/Cl[m*Ndim+n] bf16 hi/lo
// CONV 1: A = virtual im2col of (MROWS,128): col -> tap=co>>7, ch=co&127, row m+tap-1.
template<int MODE, int CONV>
__global__ void __launch_bounds__(512) k_gemm16w(
        const bf16* __restrict__ Ahi, const bf16* __restrict__ Alo,
        const bf16* __restrict__ Bhi, const bf16* __restrict__ Blo,
        float* __restrict__ C, bf16* __restrict__ Ch, bf16* __restrict__ Cl,
        int Ndim, int Kdim) {
    extern __shared__ __align__(16) unsigned char smem[];
    uint32_t sb = s2u(smem);
    int tid = threadIdx.x, lane = tid & 31, wid = tid >> 5;
    int bm = blockIdx.y * 128, bn = blockIdx.x * 128;
    int wm = wid & 3, wn = wid >> 2;

    float acc[2][4][4];
    #pragma unroll
    for (int i = 0; i < 2; i++)
        #pragma unroll
        for (int j = 0; j < 4; j++)
            #pragma unroll
            for (int q = 0; q < 4; q++) acc[i][j][q] = 0.f;

    int crow = tid >> 2, cseg = tid & 3;   // 512 threads: each (crow, cseg) exactly once
    uint32_t dst0 = (uint32_t)crow * SROW + (uint32_t)cseg * 16;
    const bf16* asrc[2] = { Ahi, Alo };
    const bf16* bsrc[2] = { Bhi, Blo };
    int bok0 = (bn + crow) < Ndim;
    int brow0 = bok0 ? bn + crow : 0;

    int nch = Kdim >> 5;

    auto load_stage = [&](int kc, int buf) {
        int k0 = kc << 5;
        uint32_t base = sb + (uint32_t)buf * SBUF + dst0;
        int co = k0 + cseg * 8;
        if (CONV) {
            int tap = co >> 7, ch = co & 127;
            int m0a = bm + crow;
            int ls0 = (m0a & (LSEQ - 1)) + tap - 1;
            int ok0 = (ls0 >= 0 && ls0 < LSEQ) ? 16 : 0;
            size_t off0 = (size_t)(m0a + tap - 1) * CIN + ch;
            #pragma unroll
            for (int t = 0; t < 2; t++) {
                cpa16(base + t * STILE, asrc[t] + off0, ok0);
                cpa16(base + (2 + t) * STILE, bsrc[t] + (size_t)brow0 * Kdim + co, bok0 ? 16 : 0);
            }
        } else {
            #pragma unroll
            for (int t = 0; t < 2; t++) {
                cpa16(base + t * STILE, asrc[t] + (size_t)(bm + crow) * Kdim + co, 16);
                cpa16(base + (2 + t) * STILE, bsrc[t] + (size_t)brow0 * Kdim + co, bok0 ? 16 : 0);
            }
        }
    };

    uint32_t ra_off = (uint32_t)(wm * 32 + (lane & 15)) * SROW + ((lane >> 4) * 8) * 2;
    uint32_t rb_off = 2 * STILE + (uint32_t)(wn * 32 + (lane & 7)) * SROW + (((lane >> 3) & 1) * 8) * 2;

    // 3-stage ring, one barrier per iteration
    load_stage(0, 0); CP_COMMIT();
    load_stage(1, 1); CP_COMMIT();
    int buf = 0, nbuf = 2;
    for (int kc = 0; kc < nch; kc++) {
        if (kc + 1 < nch) { CP_WAIT1(); } else { CP_WAIT0(); }
        __syncthreads();
        if (kc + 2 < nch) {
            load_stage(kc + 2, nbuf);
            CP_COMMIT();
        }
        uint32_t stg = sb + (uint32_t)buf * SBUF;
        #pragma unroll
        for (int kk = 0; kk < 2; kk++) {
            uint32_t ah[2][4], al[2][4], bh[4][2], bl[4][2];
            #pragma unroll
            for (int i = 0; i < 2; i++) {
                uint32_t ra = stg + ra_off + (uint32_t)(i * 16) * SROW + kk * 32;
                ldsm_x4(ah[i], ra);
                ldsm_x4(al[i], ra + STILE);
            }
            #pragma unroll
            for (int j = 0; j < 4; j++) {
                uint32_t rb = stg + rb_off + (uint32_t)(j * 8) * SROW + kk * 32;
                ldsm_x2(bh[j], rb);
                ldsm_x2(bl[j], rb + STILE);
            }
            #pragma unroll
            for (int i = 0; i < 2; i++)
                #pragma unroll
                for (int j = 0; j < 4; j++) {
                    mma_bf16(acc[i][j], ah[i], bh[j]);
                    mma_bf16(acc[i][j], ah[i], bl[j]);
                    mma_bf16(acc[i][j], al[i], bh[j]);
                }
        }
        buf  = (buf  == 2) ? 0 : buf  + 1;
        nbuf = (nbuf == 2) ? 0 : nbuf + 1;
    }

    int r0 = lane >> 2, c0l = (lane & 3) * 2;
    #pragma unroll
    for (int i = 0; i < 2; i++) {
        int m = bm + wm * 32 + i * 16 + r0;
        #pragma unroll
        for (int j = 0; j < 4; j++) {
            int n = bn + wn * 32 + j * 8 + c0l;
            if (MODE == 1) {
                size_t idx = (size_t)(n >> 11) * (256 * 2048) + (size_t)m * 2048 + (n & 2047);
                *reinterpret_cast<float2*>(C + idx) = make_float2(acc[i][j][0], acc[i][j][1]);
                *reinterpret_cast<float2*>(C + idx + 8 * 2048) = make_float2(acc[i][j][2], acc[i][j][3]);
            } else {  // MODE 2
                #pragma unroll
                for (int h = 0; h < 2; h++) {
                    float v0 = acc[i][j][h * 2], v1 = acc[i][j][h * 2 + 1];
                    uint32_t hp = bfpack(v0, v1);
                    __nv_bfloat162 hb = *reinterpret_cast<__nv_bfloat162*>(&hp);
                    uint32_t lp = bfpack(v0 - __bfloat162float(hb.x), v1 - __bfloat162float(hb.y));
                    size_t idx = (size_t)(m + h * 8) * Ndim + n;
                    *reinterpret_cast<uint32_t*>(Ch + idx) = hp;
                    *reinterpret_cast<uint32_t*>(Cl + idx) = lp;
                }
            }
        }
    }
}

// ---------------- transpose x (b,c,l) -> (b*l, c) bf16 hi/lo ----------------
__global__ void k_txp(const float* __restrict__ x) {
    __shared__ uint32_t t[32][33];
    int b = blockIdx.z;
    int l0 = blockIdx.x * 32, c0 = blockIdx.y * 32;
    int tx = threadIdx.x, ty = threadIdx.y;   // 32 x 8
    #pragma unroll
    for (int j = 0; j < 32; j += 8) {
        float v = x[(size_t)(b * CIN + c0 + ty + j) * LSEQ + l0 + tx];
        bf16 h = __float2bfloat16(v);
        bf16 l = __float2bfloat16(v - __bfloat162float(h));
        t[ty + j][tx] = (uint32_t)__bfloat16_as_ushort(h)
                      | ((uint32_t)__bfloat16_as_ushort(l) << 16);
    }
    __syncthreads();
    unsigned short* xth = reinterpret_cast<unsigned short*>(g_xth);
    unsigned short* xtl = reinterpret_cast<unsigned short*>(g_xtl);
    #pragma unroll
    for (int j = 0; j < 32; j += 8) {
        int ly = ty + j;
        uint32_t p = t[tx][ly];
        size_t idx = (size_t)(b * LSEQ + l0 + ly) * CIN + c0 + tx;
        xth[idx] = (unsigned short)(p & 0xffffu);
        xtl[idx] = (unsigned short)(p >> 16);
    }
}

__global__ void k_pwpack(const float* __restrict__ pw) {
    int tid = blockIdx.x * blockDim.x + threadIdx.x;
    int d = tid >> 9, r = tid & 511;
    int k = r >> 7, c = r & 127;
    split_store(g_pwh, g_pwl, tid, pw[(d * CIN + c) * 4 + k]);
}

// merged weight conversion (in_proj + out_proj)
__global__ void k_wcvt2(const float* __restrict__ w1, const float* __restrict__ w2) {
    int tid = blockIdx.x * blockDim.x + threadIdx.x;
    if (tid < DIP * DMODEL) {
        split_store(g_wih, g_wil, tid, w1[tid]);
    } else {
        int t2 = tid - DIP * DMODEL;
        if (t2 < DMODEL * DINNER) split_store(g_owh, g_owl, t2, w2[t2]);
    }
}

// ---------------- depthwise conv + silu + split + dt/dA (8 rows/block) ----------------
#define CTR 8
__global__ void __launch_bounds__(256) k_conv(const float* __restrict__ cw,
                                              const float* __restrict__ cb,
                                              const float* __restrict__ dt_bias,
                                              const float* __restrict__ A_log) {
    __shared__ float s[(CTR + 3) * CONVD];
    int m0 = blockIdx.x * CTR;
    int l0 = m0 & (LSEQ - 1);
    int tid = threadIdx.x;
    for (int i = tid; i < (CTR + 3) * CONVD; i += 256) {
        int r = i / CONVD, c = i - r * CONVD;
        float v = 0.f;
        if (l0 - 3 + r >= 0)
            v = g_zx[(size_t)(m0 - 3 + r) * DIP + DINNER + c];
        s[i] = v;
    }
    {
        int hh = tid;
        float db = dt_bias[hh];
        float An = -expf(A_log[hh]);
        #pragma unroll
        for (int rr = 0; rr < CTR; rr++) {
            int m = m0 + rr;
            float v = g_zx[(size_t)m * DIP + 1568 + hh] + db;
            float sp = (v > 20.f) ? v : log1pf(expf(v));
            g_dt[m * NHEADS + hh] = sp;
            g_dA[m * NHEADS + hh] = expf(sp * An);
        }
    }
    __syncthreads();
    for (int c = tid; c < CONVD; c += 256) {
        float4 w4 = *reinterpret_cast<const float4*>(cw + c * 4);
        float cbv = cb[c];
        #pragma unroll
        for (int rr = 0; rr < CTR; rr++) {
            float a = cbv + s[rr * CONVD + c] * w4.x + s[(rr + 1) * CONVD + c] * w4.y
                          + s[(rr + 2) * CONVD + c] * w4.z + s[(rr + 3) * CONVD + c] * w4.w;
            float act = a / (1.f + expf(-a));
            int m = m0 + rr;
            if (c < DINNER)    g_xs[(size_t)m * DINNER + c] = act;
            else if (c < 784)  g_Bm[m * NSTATE + c - DINNER] = act;
            else               g_Cm[m * NSTATE + c - 784] = act;
        }
    }
}

// ---------------- per-chunk local scan (QCHUNK=32, 256 blocks) ----------------
__global__ void __launch_bounds__(256) k_scan_local() {
    __shared__ float Bsh[QCHUNK * NSTATE];
    int blk = blockIdx.x;
    int hh = threadIdx.x;
    int m0 = (blk / NCHK) * LSEQ + (blk % NCHK) * QCHUNK;
    for (int i = hh; i < QCHUNK * NSTATE; i += 256) Bsh[i] = g_Bm[(size_t)m0 * NSTATE + i];
    __syncthreads();

    ull st[3][8];
    #pragma unroll
    for (int p = 0; p < 3; p++)
        #pragma unroll
        for (int q = 0; q < 8; q++) st[p][q] = 0ull;
    float dc = 1.f;

    #pragma unroll 2
    for (int s = 0; s < QCHUNK; s++) {
        size_t m = (size_t)m0 + s;
        float a  = g_dA[m * NHEADS + hh];
        float dv = g_dt[m * NHEADS + hh];
        float x0 = g_xs[m * DINNER + hh*3 + 0];
        float x1 = g_xs[m * DINNER + hh*3 + 1];
        float x2 = g_xs[m * DINNER + hh*3 + 2];
        ull a2 = pack2(a, a);
        float w0 = dv * x0, w1 = dv * x1, w2 = dv * x2;
        ull v0 = pack2(w0, w0), v1 = pack2(w1, w1), v2 = pack2(w2, w2);
        dc *= a;
        const float2* Bp = reinterpret_cast<const float2*>(Bsh + s * NSTATE);
        #pragma unroll
        for (int q = 0; q < 8; q++) {
            float2 bf = Bp[q];
            ull b2 = pack2(bf.x, bf.y);
            st[0][q] = fma2(a2, st[0][q], mul2(v0, b2));
            st[1][q] = fma2(a2, st[1][q], mul2(v1, b2));
            st[2][q] = fma2(a2, st[2][q], mul2(v2, b2));
        }
    }
    ull* outp = reinterpret_cast<ull*>(g_LS) + ((size_t)blk * NHEADS + hh) * 24;
    #pragma unroll
    for (int p = 0; p < 3; p++)
        #pragma unroll
        for (int q = 0; q < 8; q++) outp[p * 8 + q] = st[p][q];
    g_Dc[blk * NHEADS + hh] = dc;
}

// ---------------- cross-chunk scan ----------------
__global__ void k_cross() {
    int tid = blockIdx.x * blockDim.x + threadIdx.x;   // 24576
    int q  = tid % 24;
    int bh = tid / 24;
    int b  = bh >> 8, hh = bh & 255;
    ull cur = 0ull;
    const ull* LSp = reinterpret_cast<const ull*>(g_LS);
    ull* H0p = reinterpret_cast<ull*>(g_h0);
    for (int c = 0; c < NCHK; c++) {
        size_t off = ((size_t)(b * NCHK + c) * NHEADS + hh) * 24 + q;
        H0p[off] = cur;
        float dc = g_Dc[(b * NCHK + c) * NHEADS + hh];
        cur = fma2(pack2(dc, dc), cur, LSp[off]);
    }
}

// ---------------- per-chunk scan with init state, emit y ----------------
__global__ void __launch_bounds__(256) k_scan_out(const float* __restrict__ Dsk) {
    __shared__ float Bsh[QCHUNK * NSTATE];
    __shared__ float Csh[QCHUNK * NSTATE];
    int blk = blockIdx.x;
    int hh = threadIdx.x;
    int m0 = (blk / NCHK) * LSEQ + (blk % NCHK) * QCHUNK;
    for (int i = hh; i < QCHUNK * NSTATE; i += 256) {
        Bsh[i] = g_Bm[(size_t)m0 * NSTATE + i];
        Csh[i] = g_Cm[(size_t)m0 * NSTATE + i];
    }
    __syncthreads();

    ull st[3][8];
    const ull* hp = reinterpret_cast<const ull*>(g_h0) + ((size_t)blk * NHEADS + hh) * 24;
    #pragma unroll
    for (int p = 0; p < 3; p++)
        #pragma unroll
        for (int q = 0; q < 8; q++) st[p][q] = hp[p * 8 + q];
    float ds = Dsk[hh];

    #pragma unroll 2
    for (int s = 0; s < QCHUNK; s++) {
        size_t m = (size_t)m0 + s;
        float a  = g_dA[m * NHEADS + hh];
        float dv = g_dt[m * NHEADS + hh];
        float x0 = g_xs[m * DINNER + hh*3 + 0];
        float x1 = g_xs[m * DINNER + hh*3 + 1];
        float x2 = g_xs[m * DINNER + hh*3 + 2];
        ull a2 = pack2(a, a);
        float w0 = dv * x0, w1 = dv * x1, w2 = dv * x2;
        ull v0 = pack2(w0, w0), v1 = pack2(w1, w1), v2 = pack2(w2, w2);
        const float2* Bp = reinterpret_cast<const float2*>(Bsh + s * NSTATE);
        const float2* Cp = reinterpret_cast<const float2*>(Csh + s * NSTATE);
        ull y0 = 0ull, y1 = 0ull, y2 = 0ull;
        #pragma unroll
        for (int q = 0; q < 8; q++) {
            float2 bf = Bp[q];
            float2 cf = Cp[q];
            ull b2 = pack2(bf.x, bf.y);
            ull c2 = pack2(cf.x, cf.y);
            st[0][q] = fma2(a2, st[0][q], mul2(v0, b2));
            st[1][q] = fma2(a2, st[1][q], mul2(v1, b2));
            st[2][q] = fma2(a2, st[2][q], mul2(v2, b2));
            y0 = fma2(st[0][q], c2, y0);
            y1 = fma2(st[1][q], c2, y1);
            y2 = fma2(st[2][q], c2, y2);
        }
        float lo, hi;
        float* yo = g_yr + m * DINNER + hh * 3;
        unpack2(y0, lo, hi); yo[0] = lo + hi + ds * x0;
        unpack2(y1, lo, hi); yo[1] = lo + hi + ds * x1;
        unpack2(y2, lo, hi); yo[2] = lo + hi + ds * x2;
    }
}

// ---------------- gate with silu(z) + RMSNorm -> bf16 hi/lo ----------------
__global__ void k_norm(const float* __restrict__ nw) {
    int m = blockIdx.x;
    int tid = threadIdx.x;
    float vals[3];
    float ss = 0.f;
    #pragma unroll
    for (int j = 0; j < 3; j++) {
        int c = tid + j * 256;
        float z = g_zx[(size_t)m * DIP + c];
        float y = g_yr[(size_t)m * DINNER + c] * (z / (1.f + expf(-z)));
        vals[j] = y;
        ss += y * y;
    }
    #pragma unroll
    for (int o = 16; o > 0; o >>= 1) ss += __shfl_xor_sync(0xffffffffu, ss, o);
    __shared__ float red[8];
    if ((tid & 31) == 0) red[tid >> 5] = ss;
    __syncthreads();
    float tot = 0.f;
    #pragma unroll
    for (int w = 0; w < 8; w++) tot += red[w];
    float r = rsqrtf(tot * (1.f / 768.f) + 1e-5f);
    #pragma unroll
    for (int j = 0; j < 3; j++) {
        int c = tid + j * 256;
        split_store(g_ynh, g_ynl, m * DINNER + c, vals[j] * r * nw[c]);
    }
}

// ---------------- launch ----------------
extern "C" void kernel_launch(void* const* d_in, const int* in_sizes, int n_in,
                              void* d_out, int out_size) {
    const float* x        = (const float*)d_in[0];
    const float* proj_w   = (const float*)d_in[1];
    const float* in_proj  = (const float*)d_in[2];
    const float* conv_w   = (const float*)d_in[3];
    const float* conv_b   = (const float*)d_in[4];
    const float* dt_bias  = (const float*)d_in[5];
    const float* A_log    = (const float*)d_in[6];
    const float* D_skip   = (const float*)d_in[7];
    const float* norm_w   = (const float*)d_in[8];
    const float* out_proj = (const float*)d_in[9];
    float* out = (float*)d_out;

    bf16 *xth, *xtl, *pwh, *pwl, *uh, *ul, *wih, *wil, *owh, *owl, *ynh, *ynl;
    float *zx;
    cudaGetSymbolAddress((void**)&xth, g_xth); cudaGetSymbolAddress((void**)&xtl, g_xtl);
    cudaGetSymbolAddress((void**)&pwh, g_pwh); cudaGetSymbolAddress((void**)&pwl, g_pwl);
    cudaGetSymbolAddress((void**)&uh,  g_uh);  cudaGetSymbolAddress((void**)&ul,  g_ul);
    cudaGetSymbolAddress((void**)&wih, g_wih); cudaGetSymbolAddress((void**)&wil, g_wil);
    cudaGetSymbolAddress((void**)&owh, g_owh); cudaGetSymbolAddress((void**)&owl, g_owl);
    cudaGetSymbolAddress((void**)&ynh, g_ynh); cudaGetSymbolAddress((void**)&ynl, g_ynl);
    cudaGetSymbolAddress((void**)&zx,  g_zx);

    const int SM2 = 2 * SBUF;   // 81920
    const int SM3 = 3 * SBUF;   // 122880
    static int inited = 0;
    if (!inited) {
        cudaFuncSetAttribute((const void*)k_gemm_mma<0>,  cudaFuncAttributeMaxDynamicSharedMemorySize, SM2);
        cudaFuncSetAttribute((const void*)k_gemm16w<1,0>, cudaFuncAttributeMaxDynamicSharedMemorySize, SM3);
        cudaFuncSetAttribute((const void*)k_gemm16w<2,1>, cudaFuncAttributeMaxDynamicSharedMemorySize, SM3);
        inited = 1;
    }

    k_txp<<<dim3(LSEQ/32, CIN/32, BATCH), dim3(32, 8)>>>(x);
    k_pwpack<<<(DMODEL*512)/256, 256>>>(proj_w);
    k_wcvt2<<<(DIP*DMODEL + DMODEL*DINNER + 255)/256, 256>>>(in_proj, out_proj);

    // conv-proj (virtual im2col, 16 warps): u = conv(x) @ pw^T (M=8192, N=256, K=512)
    k_gemm16w<2,1><<<dim3(2, 64), 512, SM3>>>(xth, xtl, pwh, pwl, nullptr, uh, ul, DMODEL, 512);
    // in_proj (frozen 2-stage 256-thread, 2 CTA/SM): zx = u @ w^T (M=8192, N=1824, K=256)
    k_gemm_mma<0><<<dim3(15, 64), 256, SM2>>>(uh, ul, wih, wil, zx, nullptr, nullptr, DIP, DMODEL);

    k_conv<<<MROWS/CTR, 256>>>(conv_w, conv_b, dt_bias, A_log);

    k_scan_local<<<BATCH*NCHK, NHEADS>>>();
    k_cross<<<96, 256>>>();
    k_scan_out<<<BATCH*NCHK, NHEADS>>>(D_skip);

    k_norm<<<MROWS, 256>>>(norm_w);

    // out_proj (16 warps): outT = ow @ yn^T (M=256, N=8192, K=768), transposed store
    k_gemm16w<1,0><<<dim3(64, 2), 512, SM3>>>(owh, owl, ynh, ynl, out, nullptr, nullptr, MROWS, DINNER);
}

// round 17
// speedup vs baseline: 1.1133x; 1.1107x over previous
#include <cuda_runtime.h>
#include <cuda_bf16.h>
#include <cstdint>

// ---------------- problem constants ----------------
#define BATCH   4
#define LSEQ    2048
#define CIN     128
#define DMODEL  256
#define DIP     1824
#define DINNER  768
#define NHEADS  256
#define NSTATE  16
#define CONVD   800
#define MROWS   (BATCH*LSEQ)
#define QCHUNK  32
#define NCHK    (LSEQ/QCHUNK)    // 64 chunks

typedef unsigned long long ull;
typedef __nv_bfloat16 bf16;

// ---------------- scratch (fp32, tf32-rounded where GEMM operand) ----------------
__device__ float g_xt [MROWS*CIN];       // transposed x (tf32-rounded)
__device__ float g_pw [DMODEL*512];      // packed proj_w (tf32-rounded)
__device__ float g_u  [MROWS*DMODEL];    // u (tf32-rounded at epilogue)
__device__ float g_wi [DIP*DMODEL];      // in_proj w (tf32-rounded)
__device__ float g_ow [DMODEL*DINNER];   // out_proj w (tf32-rounded)
__device__ float g_yn [MROWS*DINNER];    // normed y (tf32-rounded)
__device__ float g_zx [MROWS*DIP];
__device__ float g_xs [MROWS*DINNER];
__device__ float g_Bm [MROWS*NSTATE];
__device__ float g_Cm [MROWS*NSTATE];
__device__ float g_dt [MROWS*NHEADS];
__device__ float g_dA [MROWS*NHEADS];
__device__ float g_LS [BATCH*NCHK*NHEADS*48];
__device__ float g_Dc [BATCH*NCHK*NHEADS];
__device__ float g_h0 [BATCH*NCHK*NHEADS*48];
__device__ float g_yr [MROWS*DINNER];

// ---------------- f32x2 helpers (scan kernels) ----------------
__device__ __forceinline__ ull pack2(float lo, float hi) {
    ull r; asm("mov.b64 %0, {%1,%2};" : "=l"(r) : "f"(lo), "f"(hi)); return r;
}
__device__ __forceinline__ void unpack2(ull v, float& lo, float& hi) {
    asm("mov.b64 {%0,%1}, %2;" : "=f"(lo), "=f"(hi) : "l"(v));
}
__device__ __forceinline__ ull fma2(ull a, ull b, ull c) {
    ull r; asm("fma.rn.f32x2 %0, %1, %2, %3;" : "=l"(r) : "l"(a), "l"(b), "l"(c)); return r;
}
__device__ __forceinline__ ull mul2(ull a, ull b) {
    ull r; asm("mul.rn.f32x2 %0, %1, %2;" : "=l"(r) : "l"(a), "l"(b)); return r;
}

// ---------------- tf32 / cp.async helpers ----------------
__device__ __forceinline__ uint32_t s2u(const void* p) {
    uint32_t a;
    asm("{ .reg .u64 t; cvta.to.shared.u64 t, %1; cvt.u32.u64 %0, t; }" : "=r"(a) : "l"(p));
    return a;
}
__device__ __forceinline__ float tf32r(float v) {
    uint32_t r; asm("cvt.rna.tf32.f32 %0, %1;" : "=r"(r) : "f"(v));
    return __uint_as_float(r);
}
__device__ __forceinline__ void mma_tf32(float* c, const uint32_t* a, const uint32_t* b) {
    asm volatile("mma.sync.aligned.m16n8k8.row.col.f32.tf32.tf32.f32 "
        "{%0,%1,%2,%3}, {%4,%5,%6,%7}, {%8,%9}, {%0,%1,%2,%3};"
        : "+f"(c[0]), "+f"(c[1]), "+f"(c[2]), "+f"(c[3])
        : "r"(a[0]), "r"(a[1]), "r"(a[2]), "r"(a[3]), "r"(b[0]), "r"(b[1]));
}
__device__ __forceinline__ void cpa16(uint32_t dst, const void* src, int sz) {
    asm volatile("cp.async.cg.shared.global [%0], [%1], 16, %2;"
        :: "r"(dst), "l"(src), "r"(sz) : "memory");
}
#define CP_COMMIT() asm volatile("cp.async.commit_group;" ::: "memory")
#define CP_WAIT0()  asm volatile("cp.async.wait_group 0;" ::: "memory")
#define CP_WAIT1()  asm volatile("cp.async.wait_group 1;" ::: "memory")

// ---------------- tf32 pipelined GEMM ----------------
// C[m,n] = sum_k A[m,k]*B[n,k], operands pre-rounded to tf32.
// 128x128 tile, 8 warps (2x4), warp tile 64x32, K-chunk 16 floats, 2-stage cp.async.
// smem row: 16 fp32 = 64B + 16B pad = 80B (conflict-free frag loads).
// MODE 0: C[m*Ndim+n] fp32
// MODE 1: C[(n>>11)*524288 + m*2048 + (n&2047)] fp32   (transposed out)
// MODE 2: C[m*Ndim+n] = tf32r(acc)                      (GEMM-operand output)
// CONV 1: A = virtual im2col of (MROWS,128): col co -> tap=co>>7, ch=co&127, row m+tap-1.
#define TROW   80
#define TTILE  (128*TROW)      // 10240
#define TBUF   (2*TTILE)       // 20480 per stage (A+B)
#define SMEM_T (2*TBUF)        // 40960
template<int MODE, int CONV>
__global__ void __launch_bounds__(256) k_gemm_tf32(
        const float* __restrict__ A, const float* __restrict__ Bg,
        float* __restrict__ C, int Ndim, int Kdim) {
    extern __shared__ __align__(16) unsigned char smem[];
    uint32_t sb = s2u(smem);
    int tid = threadIdx.x, lane = tid & 31, wid = tid >> 5;
    int bm = blockIdx.y * 128, bn = blockIdx.x * 128;
    int wm = wid & 1, wn = wid >> 1;

    float acc[4][4][4];
    #pragma unroll
    for (int i = 0; i < 4; i++)
        #pragma unroll
        for (int j = 0; j < 4; j++)
            #pragma unroll
            for (int q = 0; q < 4; q++) acc[i][j][q] = 0.f;

    int crow = tid >> 2, cseg = tid & 3;
    uint32_t dst0 = (uint32_t)crow * TROW + (uint32_t)cseg * 16;
    int bok0 = (bn + crow)      < Ndim;
    int bok1 = (bn + crow + 64) < Ndim;
    int brow0 = bok0 ? bn + crow      : 0;
    int brow1 = bok1 ? bn + crow + 64 : 0;

    int nch = Kdim >> 4;   // 16 floats per chunk

    auto load_stage = [&](int kc, int buf) {
        int k0 = kc << 4;
        uint32_t base = sb + (uint32_t)buf * TBUF + dst0;
        int co = k0 + cseg * 4;           // float index
        if (CONV) {
            int tap = co >> 7, ch = co & 127;
            int m0a = bm + crow, m1a = bm + crow + 64;
            int ls0 = (m0a & (LSEQ - 1)) + tap - 1;
            int ls1 = (m1a & (LSEQ - 1)) + tap - 1;
            int ok0 = (ls0 >= 0 && ls0 < LSEQ) ? 16 : 0;
            int ok1 = (ls1 >= 0 && ls1 < LSEQ) ? 16 : 0;
            cpa16(base,             A + (size_t)(m0a + tap - 1) * CIN + ch, ok0);
            cpa16(base + 64 * TROW, A + (size_t)(m1a + tap - 1) * CIN + ch, ok1);
        } else {
            cpa16(base,             A + (size_t)(bm + crow)      * Kdim + co, 16);
            cpa16(base + 64 * TROW, A + (size_t)(bm + crow + 64) * Kdim + co, 16);
        }
        cpa16(base + TTILE,             Bg + (size_t)brow0 * Kdim + co, bok0 ? 16 : 0);
        cpa16(base + TTILE + 64 * TROW, Bg + (size_t)brow1 * Kdim + co, bok1 ? 16 : 0);
    };

    load_stage(0, 0);
    CP_COMMIT();

    int fr = lane >> 2, fc = lane & 3;    // frag row/col within 8x4 pattern

    for (int kc = 0; kc < nch; kc++) {
        if (kc + 1 < nch) {
            load_stage(kc + 1, (kc + 1) & 1);
            CP_COMMIT();
            CP_WAIT1();
        } else {
            CP_WAIT0();
        }
        __syncthreads();
        uint32_t stg = sb + (uint32_t)(kc & 1) * TBUF;
        #pragma unroll
        for (int kk = 0; kk < 2; kk++) {
            uint32_t av[4][4], bv[4][2];
            #pragma unroll
            for (int i = 0; i < 4; i++) {
                uint32_t ro = stg + (uint32_t)(wm * 64 + i * 16 + fr) * TROW + (kk * 8 + fc) * 4;
                av[i][0] = *reinterpret_cast<const uint32_t*>(smem + (ro - sb));
                av[i][1] = *reinterpret_cast<const uint32_t*>(smem + (ro - sb) + 8 * TROW);
                av[i][2] = *reinterpret_cast<const uint32_t*>(smem + (ro - sb) + 16);
                av[i][3] = *reinterpret_cast<const uint32_t*>(smem + (ro - sb) + 8 * TROW + 16);
            }
            #pragma unroll
            for (int j = 0; j < 4; j++) {
                uint32_t ro = stg + TTILE + (uint32_t)(wn * 32 + j * 8 + fr) * TROW + (kk * 8 + fc) * 4;
                bv[j][0] = *reinterpret_cast<const uint32_t*>(smem + (ro - sb));
                bv[j][1] = *reinterpret_cast<const uint32_t*>(smem + (ro - sb) + 16);
            }
            #pragma unroll
            for (int i = 0; i < 4; i++)
                #pragma unroll
                for (int j = 0; j < 4; j++)
                    mma_tf32(acc[i][j], av[i], bv[j]);
        }
        __syncthreads();
    }

    int r0 = lane >> 2, c0l = (lane & 3) * 2;
    #pragma unroll
    for (int i = 0; i < 4; i++) {
        int m = bm + wm * 64 + i * 16 + r0;
        #pragma unroll
        for (int j = 0; j < 4; j++) {
            int n = bn + wn * 32 + j * 8 + c0l;
            if (MODE == 0) {
                if (n + 2 <= Ndim) {
                    *reinterpret_cast<float2*>(C + (size_t)m * Ndim + n) =
                        make_float2(acc[i][j][0], acc[i][j][1]);
                    *reinterpret_cast<float2*>(C + (size_t)(m + 8) * Ndim + n) =
                        make_float2(acc[i][j][2], acc[i][j][3]);
                }
            } else if (MODE == 1) {
                size_t idx = (size_t)(n >> 11) * (256 * 2048) + (size_t)m * 2048 + (n & 2047);
                *reinterpret_cast<float2*>(C + idx) = make_float2(acc[i][j][0], acc[i][j][1]);
                *reinterpret_cast<float2*>(C + idx + 8 * 2048) = make_float2(acc[i][j][2], acc[i][j][3]);
            } else {
                if (n + 2 <= Ndim) {
                    *reinterpret_cast<float2*>(C + (size_t)m * Ndim + n) =
                        make_float2(tf32r(acc[i][j][0]), tf32r(acc[i][j][1]));
                    *reinterpret_cast<float2*>(C + (size_t)(m + 8) * Ndim + n) =
                        make_float2(tf32r(acc[i][j][2]), tf32r(acc[i][j][3]));
                }
            }
        }
    }
}

// ---------------- transpose x (b,c,l) -> (b*l, c) fp32 tf32-rounded ----------------
__global__ void k_txp(const float* __restrict__ x) {
    __shared__ float t[32][33];
    int b = blockIdx.z;
    int l0 = blockIdx.x * 32, c0 = blockIdx.y * 32;
    int tx = threadIdx.x, ty = threadIdx.y;   // 32 x 8
    #pragma unroll
    for (int j = 0; j < 32; j += 8)
        t[ty + j][tx] = tf32r(x[(size_t)(b * CIN + c0 + ty + j) * LSEQ + l0 + tx]);
    __syncthreads();
    #pragma unroll
    for (int j = 0; j < 32; j += 8)
        g_xt[(size_t)(b * LSEQ + l0 + ty + j) * CIN + c0 + tx] = t[tx][ty + j];
}

__global__ void k_pwpack(const float* __restrict__ pw) {
    int tid = blockIdx.x * blockDim.x + threadIdx.x;
    int d = tid >> 9, r = tid & 511;
    int k = r >> 7, c = r & 127;
    g_pw[tid] = tf32r(pw[(d * CIN + c) * 4 + k]);
}

// merged weight rounding (in_proj + out_proj)
__global__ void k_wround(const float* __restrict__ w1, const float* __restrict__ w2) {
    int tid = blockIdx.x * blockDim.x + threadIdx.x;
    if (tid < DIP * DMODEL) {
        g_wi[tid] = tf32r(w1[tid]);
    } else {
        int t2 = tid - DIP * DMODEL;
        if (t2 < DMODEL * DINNER) g_ow[t2] = tf32r(w2[t2]);
    }
}

// ---------------- depthwise conv + silu + split + dt/dA (8 rows/block) ----------------
#define CTR 8
__global__ void __launch_bounds__(256) k_conv(const float* __restrict__ cw,
                                              const float* __restrict__ cb,
                                              const float* __restrict__ dt_bias,
                                              const float* __restrict__ A_log) {
    __shared__ float s[(CTR + 3) * CONVD];
    int m0 = blockIdx.x * CTR;
    int l0 = m0 & (LSEQ - 1);
    int tid = threadIdx.x;
    for (int i = tid; i < (CTR + 3) * CONVD; i += 256) {
        int r = i / CONVD, c = i - r * CONVD;
        float v = 0.f;
        if (l0 - 3 + r >= 0)
            v = g_zx[(size_t)(m0 - 3 + r) * DIP + DINNER + c];
        s[i] = v;
    }
    {
        int hh = tid;
        float db = dt_bias[hh];
        float An = -expf(A_log[hh]);
        #pragma unroll
        for (int rr = 0; rr < CTR; rr++) {
            int m = m0 + rr;
            float v = g_zx[(size_t)m * DIP + 1568 + hh] + db;
            float sp = (v > 20.f) ? v : log1pf(expf(v));
            g_dt[m * NHEADS + hh] = sp;
            g_dA[m * NHEADS + hh] = expf(sp * An);
        }
    }
    __syncthreads();
    for (int c = tid; c < CONVD; c += 256) {
        float4 w4 = *reinterpret_cast<const float4*>(cw + c * 4);
        float cbv = cb[c];
        #pragma unroll
        for (int rr = 0; rr < CTR; rr++) {
            float a = cbv + s[rr * CONVD + c] * w4.x + s[(rr + 1) * CONVD + c] * w4.y
                          + s[(rr + 2) * CONVD + c] * w4.z + s[(rr + 3) * CONVD + c] * w4.w;
            float act = a / (1.f + expf(-a));
            int m = m0 + rr;
            if (c < DINNER)    g_xs[(size_t)m * DINNER + c] = act;
            else if (c < 784)  g_Bm[m * NSTATE + c - DINNER] = act;
            else               g_Cm[m * NSTATE + c - 784] = act;
        }
    }
}

// ---------------- per-chunk local scan (QCHUNK=32, 256 blocks) ----------------
__global__ void __launch_bounds__(256) k_scan_local() {
    __shared__ float Bsh[QCHUNK * NSTATE];
    int blk = blockIdx.x;
    int hh = threadIdx.x;
    int m0 = (blk / NCHK) * LSEQ + (blk % NCHK) * QCHUNK;
    for (int i = hh; i < QCHUNK * NSTATE; i += 256) Bsh[i] = g_Bm[(size_t)m0 * NSTATE + i];
    __syncthreads();

    ull st[3][8];
    #pragma unroll
    for (int p = 0; p < 3; p++)
        #pragma unroll
        for (int q = 0; q < 8; q++) st[p][q] = 0ull;
    float dc = 1.f;

    #pragma unroll 2
    for (int s = 0; s < QCHUNK; s++) {
        size_t m = (size_t)m0 + s;
        float a  = g_dA[m * NHEADS + hh];
        float dv = g_dt[m * NHEADS + hh];
        float x0 = g_xs[m * DINNER + hh*3 + 0];
        float x1 = g_xs[m * DINNER + hh*3 + 1];
        float x2 = g_xs[m * DINNER + hh*3 + 2];
        ull a2 = pack2(a, a);
        float w0 = dv * x0, w1 = dv * x1, w2 = dv * x2;
        ull v0 = pack2(w0, w0), v1 = pack2(w1, w1), v2 = pack2(w2, w2);
        dc *= a;
        const float2* Bp = reinterpret_cast<const float2*>(Bsh + s * NSTATE);
        #pragma unroll
        for (int q = 0; q < 8; q++) {
            float2 bf = Bp[q];
            ull b2 = pack2(bf.x, bf.y);
            st[0][q] = fma2(a2, st[0][q], mul2(v0, b2));
            st[1][q] = fma2(a2, st[1][q], mul2(v1, b2));
            st[2][q] = fma2(a2, st[2][q], mul2(v2, b2));
        }
    }
    ull* outp = reinterpret_cast<ull*>(g_LS) + ((size_t)blk * NHEADS + hh) * 24;
    #pragma unroll
    for (int p = 0; p < 3; p++)
        #pragma unroll
        for (int q = 0; q < 8; q++) outp[p * 8 + q] = st[p][q];
    g_Dc[blk * NHEADS + hh] = dc;
}

// ---------------- cross-chunk scan ----------------
__global__ void k_cross() {
    int tid = blockIdx.x * blockDim.x + threadIdx.x;   // 24576
    int q  = tid % 24;
    int bh = tid / 24;
    int b  = bh >> 8, hh = bh & 255;
    ull cur = 0ull;
    const ull* LSp = reinterpret_cast<const ull*>(g_LS);
    ull* H0p = reinterpret_cast<ull*>(g_h0);
    for (int c = 0; c < NCHK; c++) {
        size_t off = ((size_t)(b * NCHK + c) * NHEADS + hh) * 24 + q;
        H0p[off] = cur;
        float dc = g_Dc[(b * NCHK + c) * NHEADS + hh];
        cur = fma2(pack2(dc, dc), cur, LSp[off]);
    }
}

// ---------------- per-chunk scan with init state, emit y ----------------
__global__ void __launch_bounds__(256) k_scan_out(const float* __restrict__ Dsk) {
    __shared__ float Bsh[QCHUNK * NSTATE];
    __shared__ float Csh[QCHUNK * NSTATE];
    int blk = blockIdx.x;
    int hh = threadIdx.x;
    int m0 = (blk / NCHK) * LSEQ + (blk % NCHK) * QCHUNK;
    for (int i = hh; i < QCHUNK * NSTATE; i += 256) {
        Bsh[i] = g_Bm[(size_t)m0 * NSTATE + i];
        Csh[i] = g_Cm[(size_t)m0 * NSTATE + i];
    }
    __syncthreads();

    ull st[3][8];
    const ull* hp = reinterpret_cast<const ull*>(g_h0) + ((size_t)blk * NHEADS + hh) * 24;
    #pragma unroll
    for (int p = 0; p < 3; p++)
        #pragma unroll
        for (int q = 0; q < 8; q++) st[p][q] = hp[p * 8 + q];
    float ds = Dsk[hh];

    #pragma unroll 2
    for (int s = 0; s < QCHUNK; s++) {
        size_t m = (size_t)m0 + s;
        float a  = g_dA[m * NHEADS + hh];
        float dv = g_dt[m * NHEADS + hh];
        float x0 = g_xs[m * DINNER + hh*3 + 0];
        float x1 = g_xs[m * DINNER + hh*3 + 1];
        float x2 = g_xs[m * DINNER + hh*3 + 2];
        ull a2 = pack2(a, a);
        float w0 = dv * x0, w1 = dv * x1, w2 = dv * x2;
        ull v0 = pack2(w0, w0), v1 = pack2(w1, w1), v2 = pack2(w2, w2);
        const float2* Bp = reinterpret_cast<const float2*>(Bsh + s * NSTATE);
        const float2* Cp = reinterpret_cast<const float2*>(Csh + s * NSTATE);
        ull y0 = 0ull, y1 = 0ull, y2 = 0ull;
        #pragma unroll
        for (int q = 0; q < 8; q++) {
            float2 bf = Bp[q];
            float2 cf = Cp[q];
            ull b2 = pack2(bf.x, bf.y);
            ull c2 = pack2(cf.x, cf.y);
            st[0][q] = fma2(a2, st[0][q], mul2(v0, b2));
            st[1][q] = fma2(a2, st[1][q], mul2(v1, b2));
            st[2][q] = fma2(a2, st[2][q], mul2(v2, b2));
            y0 = fma2(st[0][q], c2, y0);
            y1 = fma2(st[1][q], c2, y1);
            y2 = fma2(st[2][q], c2, y2);
        }
        float lo, hi;
        float* yo = g_yr + m * DINNER + hh * 3;
        unpack2(y0, lo, hi); yo[0] = lo + hi + ds * x0;
        unpack2(y1, lo, hi); yo[1] = lo + hi + ds * x1;
        unpack2(y2, lo, hi); yo[2] = lo + hi + ds * x2;
    }
}

// ---------------- gate with silu(z) + RMSNorm -> fp32 tf32-rounded ----------------
__global__ void k_norm(const float* __restrict__ nw) {
    int m = blockIdx.x;
    int tid = threadIdx.x;
    float vals[3];
    float ss = 0.f;
    #pragma unroll
    for (int j = 0; j < 3; j++) {
        int c = tid + j * 256;
        float z = g_zx[(size_t)m * DIP + c];
        float y = g_yr[(size_t)m * DINNER + c] * (z / (1.f + expf(-z)));
        vals[j] = y;
        ss += y * y;
    }
    #pragma unroll
    for (int o = 16; o > 0; o >>= 1) ss += __shfl_xor_sync(0xffffffffu, ss, o);
    __shared__ float red[8];
    if ((tid & 31) == 0) red[tid >> 5] = ss;
    __syncthreads();
    float tot = 0.f;
    #pragma unroll
    for (int w = 0; w < 8; w++) tot += red[w];
    float r = rsqrtf(tot * (1.f / 768.f) + 1e-5f);
    #pragma unroll
    for (int j = 0; j < 3; j++) {
        int c = tid + j * 256;
        g_yn[(size_t)m * DINNER + c] = tf32r(vals[j] * r * nw[c]);
    }
}

// ---------------- launch ----------------
extern "C" void kernel_launch(void* const* d_in, const int* in_sizes, int n_in,
                              void* d_out, int out_size) {
    const float* x        = (const float*)d_in[0];
    const float* proj_w   = (const float*)d_in[1];
    const float* in_proj  = (const float*)d_in[2];
    const float* conv_w   = (const float*)d_in[3];
    const float* conv_b   = (const float*)d_in[4];
    const float* dt_bias  = (const float*)d_in[5];
    const float* A_log    = (const float*)d_in[6];
    const float* D_skip   = (const float*)d_in[7];
    const float* norm_w   = (const float*)d_in[8];
    const float* out_proj = (const float*)d_in[9];
    float* out = (float*)d_out;

    float *xt, *pw, *u, *wi, *ow, *yn, *zx;
    cudaGetSymbolAddress((void**)&xt, g_xt);
    cudaGetSymbolAddress((void**)&pw, g_pw);
    cudaGetSymbolAddress((void**)&u,  g_u);
    cudaGetSymbolAddress((void**)&wi, g_wi);
    cudaGetSymbolAddress((void**)&ow, g_ow);
    cudaGetSymbolAddress((void**)&yn, g_yn);
    cudaGetSymbolAddress((void**)&zx, g_zx);

    static int inited = 0;
    if (!inited) {
        cudaFuncSetAttribute((const void*)k_gemm_tf32<2,1>, cudaFuncAttributeMaxDynamicSharedMemorySize, SMEM_T);
        cudaFuncSetAttribute((const void*)k_gemm_tf32<0,0>, cudaFuncAttributeMaxDynamicSharedMemorySize, SMEM_T);
        cudaFuncSetAttribute((const void*)k_gemm_tf32<1,0>, cudaFuncAttributeMaxDynamicSharedMemorySize, SMEM_T);
        inited = 1;
    }

    k_txp<<<dim3(LSEQ/32, CIN/32, BATCH), dim3(32, 8)>>>(x);
    k_pwpack<<<(DMODEL*512)/256, 256>>>(proj_w);
    k_wround<<<(DIP*DMODEL + DMODEL*DINNER + 255)/256, 256>>>(in_proj, out_proj);

    // conv-proj (virtual im2col): u = conv(x) @ pw^T (M=8192, N=256, K=512) -> tf32-rounded
    k_gemm_tf32<2,1><<<dim3(2, 64), 256, SMEM_T>>>(xt, pw, u, DMODEL, 512);
    // in_proj: zx = u @ wi^T (M=8192, N=1824, K=256) -> fp32
    k_gemm_tf32<0,0><<<dim3(15, 64), 256, SMEM_T>>>(u, wi, zx, DIP, DMODEL);

    k_conv<<<MROWS/CTR, 256>>>(conv_w, conv_b, dt_bias, A_log);

    k_scan_local<<<BATCH*NCHK, NHEADS>>>();
    k_cross<<<96, 256>>>();
    k_scan_out<<<BATCH*NCHK, NHEADS>>>(D_skip);

    k_norm<<<MROWS, 256>>>(norm_w);

    // out_proj swapped: outT = ow @ yn^T (M=256, N=8192, K=768), transposed store
    k_gemm_tf32<1,0><<<dim3(64, 2), 256, SMEM_T>>>(ow, yn, out, MROWS, DINNER);
}